// round 1
// baseline (speedup 1.0000x reference)
#include <cuda_runtime.h>
#include <math.h>

// Problem constants (fixed-shape problem)
#define BB 4
#define HH 180
#define WW 180
#define SPATIAL (HH * WW)        // 32400
#define C_L 128
#define C_C 128
#define CH_ALL 512
#define CH_HID 170
#define C_OUT 256

// ---------------- device scratch (static: no runtime allocation allowed) ----
__device__ __align__(16) float g_imgT[SPATIAL * C_C];       // [pixel][channel], batch 0 only
__device__ unsigned g_keys[BB * CH_ALL];                    // encoded min/max keys
__device__ __align__(16) float g_att_l[BB * C_L];
__device__ __align__(16) float g_att_c[BB * C_C];

// Order-preserving float <-> uint encoding for atomic min/max
__device__ __forceinline__ unsigned enc_f(float x) {
    unsigned u = __float_as_uint(x);
    return (u & 0x80000000u) ? ~u : (u | 0x80000000u);
}
__device__ __forceinline__ float dec_f(unsigned k) {
    unsigned u = (k & 0x80000000u) ? (k ^ 0x80000000u) : ~k;
    return __uint_as_float(u);
}

// ---------------- kernel 0: init min/max keys --------------------------------
__global__ void init_keys_kernel() {
    int i = blockIdx.x * blockDim.x + threadIdx.x;
    if (i >= BB * CH_ALL) return;
    int slot = i & (CH_ALL - 1);
    // per batch: [0,128) lmin, [128,256) lmax, [256,384) cmin, [384,512) cmax
    bool is_min = (slot < 128) || (slot >= 256 && slot < 384);
    g_keys[i] = is_min ? 0xFFFFFFFFu : 0x00000000u;
}

// ---------------- kernel 1: transpose img_bev[0]  [C][P] -> [P][C] -----------
__global__ void transpose_kernel(const float* __restrict__ img) {
    __shared__ float tile[32][33];
    int p0 = blockIdx.x * 32;
    int c0 = blockIdx.y * 32;
    int tx = threadIdx.x;   // 0..31
    int ty = threadIdx.y;   // 0..7
#pragma unroll
    for (int j = 0; j < 4; ++j) {
        int c = c0 + ty + j * 8;
        int p = p0 + tx;
        if (p < SPATIAL) tile[ty + j * 8][tx] = img[c * SPATIAL + p];
    }
    __syncthreads();
#pragma unroll
    for (int j = 0; j < 4; ++j) {
        int p = p0 + ty + j * 8;
        int c = c0 + tx;
        if (p < SPATIAL) g_imgT[p * C_C + c] = tile[tx][ty + j * 8];
    }
}

// ---------------- kernel 2: per-batch segment min/max ------------------------
// Each thread owns one of 256 channels (0..127 lidar, 128..255 cam) and scans
// a 256-row chunk keeping running min/max; batch_idx is sorted, so flushes on
// batch change are rare and block-uniform.
#define MM_CHUNK 256

__device__ __forceinline__ void flush_mm(int b, int c, float mn, float mx) {
    int msl, xsl;
    if (c < 128) { msl = c;            xsl = 128 + c; }
    else         { msl = 256 + c - 128; xsl = 384 + c - 128; }
    atomicMin(&g_keys[b * CH_ALL + msl], enc_f(mn));
    atomicMax(&g_keys[b * CH_ALL + xsl], enc_f(mx));
}

__global__ void __launch_bounds__(256) minmax_kernel(
    const float* __restrict__ lidar,
    const int* __restrict__ batch_idx,
    const int* __restrict__ y_idx,
    const int* __restrict__ x_idx,
    int N)
{
    __shared__ int sb[MM_CHUNK];
    __shared__ int sr[MM_CHUNK];
    int tid = threadIdx.x;
    int n0 = blockIdx.x * MM_CHUNK;
    int cnt = N - n0; if (cnt > MM_CHUNK) cnt = MM_CHUNK;
    if (cnt <= 0) return;

    if (tid < cnt) {
        int n = n0 + tid;
        int b = batch_idx[n];
        int r = b * SPATIAL + y_idx[n] * WW + x_idx[n];
        if (r > SPATIAL - 2) r = SPATIAL - 2;
        sb[tid] = b;
        sr[tid] = r;
    }
    __syncthreads();

    const int c = tid;  // channel 0..255
    float mn = INFINITY, mx = -INFINITY;
    int cur = sb[0];
    for (int i = 0; i < cnt; ++i) {
        int b = sb[i];
        if (b != cur) {                 // block-uniform branch (sorted batches)
            flush_mm(cur, c, mn, mx);
            cur = b; mn = INFINITY; mx = -INFINITY;
        }
        float v = (c < 128) ? lidar[(size_t)(n0 + i) * C_L + c]
                            : g_imgT[(size_t)sr[i] * C_C + (c - 128)];
        mn = fminf(mn, v);
        mx = fmaxf(mx, v);
    }
    flush_mm(cur, c, mn, mx);
}

// ---------------- kernel 3: tiny gating MLPs (single block) ------------------
__global__ void __launch_bounds__(256) mlp_kernel(
    const float* __restrict__ Wl1, const float* __restrict__ Wl2,
    const float* __restrict__ Wc1, const float* __restrict__ Wc2)
{
    __shared__ float cat[BB][CH_ALL];           // 8 KB
    __shared__ float hid[2][BB][176];           // 170 padded to 176
    int tid = threadIdx.x;

    for (int i = tid; i < BB * CH_ALL; i += 256)
        cat[i >> 9][i & 511] = dec_f(g_keys[i]);
    __syncthreads();

    for (int idx = tid; idx < 2 * BB * CH_HID; idx += 256) {
        int net = idx / (BB * CH_HID);
        int rem = idx % (BB * CH_HID);
        int b = rem / CH_HID;
        int j = rem % CH_HID;
        const float* W = net ? Wc1 : Wl1;       // [512][170]
        float s = 0.f;
        for (int k = 0; k < CH_ALL; ++k) s = fmaf(cat[b][k], W[k * CH_HID + j], s);
        hid[net][b][j] = fmaxf(s, 0.f);
    }
    __syncthreads();

    for (int idx = tid; idx < 2 * BB * 128; idx += 256) {
        int net = idx / (BB * 128);
        int rem = idx % (BB * 128);
        int b = rem >> 7;
        int cc = rem & 127;
        const float* W2 = net ? Wc2 : Wl2;      // [170][128]
        float s = 0.f;
        for (int k = 0; k < CH_HID; ++k) s = fmaf(hid[net][b][k], W2[k * 128 + cc], s);
        float v = fmaxf(s, 0.f);
        float att = 1.f / (1.f + expf(-v));
        if (net) g_att_c[b * 128 + cc] = att;
        else     g_att_l[b * 128 + cc] = att;
    }
}

// ---------------- kernel 4: fused gate + GEMM1 + ReLU + GEMM2 + ReLU ---------
// Block: 256 threads, 64 rows x 256 cols output tile, 8x8 register tile/thread.
// smem: fused/h tile [64][256] (reused), weight k-panel [32][256].
#define BM 64
#define SMEM_D (BM * 256 * 4 + 32 * 256 * 4 + 2 * BM * 4)

__device__ __forceinline__ void gemm_256x256(
    const float4* __restrict__ W4,   // weights [256][256] viewed as float4
    const float* __restrict__ src_s, // [64][256] in smem
    float4* wp4,                     // [32][64] float4 panel in smem
    float acc[8][8], int tid, int ty, int tx)
{
#pragma unroll 1
    for (int kp = 0; kp < 8; ++kp) {
        __syncthreads();             // protect previous panel / previous writers
#pragma unroll
        for (int i = 0; i < 8; ++i) {
            int idx = tid + i * 256; // 0..2047 float4s of the 32x256 panel
            wp4[idx] = W4[kp * 2048 + idx];
        }
        __syncthreads();
#pragma unroll
        for (int kk = 0; kk < 32; ++kk) {
            float a[8];
#pragma unroll
            for (int i = 0; i < 8; ++i)
                a[i] = src_s[(ty * 8 + i) * 256 + kp * 32 + kk];
            float4 b0 = wp4[kk * 64 + tx * 2];
            float4 b1 = wp4[kk * 64 + tx * 2 + 1];
            float bb[8] = {b0.x, b0.y, b0.z, b0.w, b1.x, b1.y, b1.z, b1.w};
#pragma unroll
            for (int i = 0; i < 8; ++i)
#pragma unroll
                for (int j = 0; j < 8; ++j)
                    acc[i][j] = fmaf(a[i], bb[j], acc[i][j]);
        }
    }
}

__global__ void __launch_bounds__(256, 2) fused_kernel(
    const float* __restrict__ lidar,
    const int* __restrict__ batch_idx,
    const int* __restrict__ y_idx,
    const int* __restrict__ x_idx,
    const float* __restrict__ Wf1,
    const float* __restrict__ Wf2,
    float* __restrict__ out,
    int N)
{
    extern __shared__ float sm[];
    float* fused_s = sm;                       // [64][256]
    float* wp      = sm + BM * 256;            // [32][256]
    int*   sb      = (int*)(wp + 32 * 256);    // [64]
    int*   sr      = sb + BM;                  // [64]
    float4* fused4 = (float4*)fused_s;
    float4* wp4    = (float4*)wp;

    const int tid = threadIdx.x;
    const int tx = tid & 31;
    const int ty = tid >> 5;
    const int n0 = blockIdx.x * BM;

    if (tid < BM) {
        int n = n0 + tid;
        int b = 0, r = 0;
        if (n < N) {
            b = batch_idx[n];
            r = b * SPATIAL + y_idx[n] * WW + x_idx[n];
            if (r > SPATIAL - 2) r = SPATIAL - 2;
        }
        sb[tid] = b;
        sr[tid] = r;
    }
    __syncthreads();

    // Phase 1: gated feature assembly -> fused_s[m][k]  (k: 0..127 lidar, 128..255 cam)
    const float4* lidar4 = (const float4*)lidar;
    const float4* imgT4  = (const float4*)g_imgT;
    const float4* attl4  = (const float4*)g_att_l;
    const float4* attc4  = (const float4*)g_att_c;
#pragma unroll
    for (int i = 0; i < 8; ++i) {
        int idx = tid + i * 256;     // 0..2047
        int m  = idx >> 5;           // row in tile
        int cg = idx & 31;           // float4 channel group (0..31)
        int n  = n0 + m;
        int b  = sb[m];
        float4 L = make_float4(0.f, 0.f, 0.f, 0.f);
        float4 C = L;
        if (n < N) {
            L = lidar4[(size_t)n * 32 + cg];
            C = imgT4[(size_t)sr[m] * 32 + cg];
        }
        float4 gl = attl4[b * 32 + cg];
        float4 gc = attc4[b * 32 + cg];
        float4 vl = make_float4(L.x * gl.x, L.y * gl.y, L.z * gl.z, L.w * gl.w);
        float4 vc = make_float4(C.x * gc.x, C.y * gc.y, C.z * gc.z, C.w * gc.w);
        fused4[m * 64 + cg]      = vl;
        fused4[m * 64 + 32 + cg] = vc;
    }
    // (gemm's internal leading __syncthreads covers these writes)

    // GEMM1: h = relu(fused @ Wf1)
    float acc[8][8];
#pragma unroll
    for (int i = 0; i < 8; ++i)
#pragma unroll
        for (int j = 0; j < 8; ++j) acc[i][j] = 0.f;
    gemm_256x256((const float4*)Wf1, fused_s, wp4, acc, tid, ty, tx);

    __syncthreads();   // everyone done reading fused_s before overwrite with h
#pragma unroll
    for (int i = 0; i < 8; ++i) {
        int m = ty * 8 + i;
        float4 v0 = make_float4(fmaxf(acc[i][0], 0.f), fmaxf(acc[i][1], 0.f),
                                fmaxf(acc[i][2], 0.f), fmaxf(acc[i][3], 0.f));
        float4 v1 = make_float4(fmaxf(acc[i][4], 0.f), fmaxf(acc[i][5], 0.f),
                                fmaxf(acc[i][6], 0.f), fmaxf(acc[i][7], 0.f));
        fused4[m * 64 + tx * 2]     = v0;
        fused4[m * 64 + tx * 2 + 1] = v1;
    }

    // GEMM2: out = relu(h @ Wf2)
#pragma unroll
    for (int i = 0; i < 8; ++i)
#pragma unroll
        for (int j = 0; j < 8; ++j) acc[i][j] = 0.f;
    gemm_256x256((const float4*)Wf2, fused_s, wp4, acc, tid, ty, tx);

    float4* out4 = (float4*)out;
#pragma unroll
    for (int i = 0; i < 8; ++i) {
        int n = n0 + ty * 8 + i;
        if (n < N) {
            float4 v0 = make_float4(fmaxf(acc[i][0], 0.f), fmaxf(acc[i][1], 0.f),
                                    fmaxf(acc[i][2], 0.f), fmaxf(acc[i][3], 0.f));
            float4 v1 = make_float4(fmaxf(acc[i][4], 0.f), fmaxf(acc[i][5], 0.f),
                                    fmaxf(acc[i][6], 0.f), fmaxf(acc[i][7], 0.f));
            out4[(size_t)n * 64 + tx * 2]     = v0;
            out4[(size_t)n * 64 + tx * 2 + 1] = v1;
        }
    }
}

// ---------------- host launcher ----------------------------------------------
extern "C" void kernel_launch(void* const* d_in, const int* in_sizes, int n_in,
                              void* d_out, int out_size)
{
    // Identify inputs by element count (robust to metadata vs signature order;
    // relative order within equal-size groups matches both orderings).
    int iL = -1, iImg = -1, iB = -1, iY = -1, iX = -1;
    int iWl1 = -1, iWl2 = -1, iWc1 = -1, iWc2 = -1, iWf1 = -1, iWf2 = -1;
    for (int i = 0; i < n_in; ++i) {
        int s = in_sizes[i];
        if      (s == BB * C_C * SPATIAL)      iImg = i;                       // 16,588,800
        else if (s == CH_ALL * CH_HID)         { if (iWl1 < 0) iWl1 = i; else iWc1 = i; }
        else if (s == CH_HID * C_L)            { if (iWl2 < 0) iWl2 = i; else iWc2 = i; }
        else if (s == C_OUT * C_OUT)           { if (iWf1 < 0) iWf1 = i; else iWf2 = i; }
        else if (s % C_L == 0 && s >= 1000000) iL = i;                         // lidar [N,128]
        else                                   { if (iB < 0) iB = i; else if (iY < 0) iY = i; else iX = i; }
    }
    const float* lidar = (const float*)d_in[iL];
    const float* img   = (const float*)d_in[iImg];
    const int*   bidx  = (const int*)d_in[iB];
    const int*   yidx  = (const int*)d_in[iY];
    const int*   xidx  = (const int*)d_in[iX];
    const float* Wl1   = (const float*)d_in[iWl1];
    const float* Wl2   = (const float*)d_in[iWl2];
    const float* Wc1   = (const float*)d_in[iWc1];
    const float* Wc2   = (const float*)d_in[iWc2];
    const float* Wf1   = (const float*)d_in[iWf1];
    const float* Wf2   = (const float*)d_in[iWf2];
    float* out = (float*)d_out;
    const int N = in_sizes[iL] / C_L;

    static int smem_set = 0;
    (void)smem_set;
    cudaFuncSetAttribute(fused_kernel, cudaFuncAttributeMaxDynamicSharedMemorySize, SMEM_D);

    init_keys_kernel<<<(BB * CH_ALL + 255) / 256, 256>>>();
    transpose_kernel<<<dim3((SPATIAL + 31) / 32, C_C / 32), dim3(32, 8)>>>(img);
    minmax_kernel<<<(N + MM_CHUNK - 1) / MM_CHUNK, 256>>>(lidar, bidx, yidx, xidx, N);
    mlp_kernel<<<1, 256>>>(Wl1, Wl2, Wc1, Wc2);
    fused_kernel<<<(N + BM - 1) / BM, 256, SMEM_D>>>(lidar, bidx, yidx, xidx, Wf1, Wf2, out, N);
    (void)out_size;
}

// round 2
// speedup vs baseline: 1.2558x; 1.2558x over previous
#include <cuda_runtime.h>
#include <math.h>

// Problem constants (fixed-shape problem)
#define BB 4
#define HH 180
#define WW 180
#define SPATIAL (HH * WW)        // 32400
#define C_L 128
#define C_C 128
#define CH_ALL 512
#define CH_HID 170
#define C_OUT 256

typedef unsigned long long u64;

// ---------------- device scratch ---------------------------------------------
__device__ __align__(16) float g_imgT[SPATIAL * C_C];       // [pixel][channel], batch 0 only
__device__ unsigned g_keys[BB * CH_ALL];                    // encoded min/max keys
__device__ __align__(16) float g_hid[2][BB][CH_HID];        // MLP hidden activations
__device__ __align__(16) float g_att_l[BB * C_L];
__device__ __align__(16) float g_att_c[BB * C_C];

// Order-preserving float <-> uint encoding for atomic min/max
__device__ __forceinline__ unsigned enc_f(float x) {
    unsigned u = __float_as_uint(x);
    return (u & 0x80000000u) ? ~u : (u | 0x80000000u);
}
__device__ __forceinline__ float dec_f(unsigned k) {
    unsigned u = (k & 0x80000000u) ? (k ^ 0x80000000u) : ~k;
    return __uint_as_float(u);
}

// ---------------- packed f32x2 helpers (sm_103a FFMA2) ------------------------
__device__ __forceinline__ u64 pack_dup(float x) {
    u64 r; asm("mov.b64 %0, {%1, %1};" : "=l"(r) : "f"(x)); return r;
}
__device__ __forceinline__ void ffma2(u64 &d, u64 a, u64 b) {
    asm("fma.rn.f32x2 %0, %1, %2, %0;" : "+l"(d) : "l"(a), "l"(b));
}
__device__ __forceinline__ float2 unpk(u64 v) {
    float lo, hi; asm("mov.b64 {%0, %1}, %2;" : "=f"(lo), "=f"(hi) : "l"(v));
    return make_float2(lo, hi);
}

// ---------------- kernel 0: init min/max keys --------------------------------
__global__ void init_keys_kernel() {
    int i = blockIdx.x * blockDim.x + threadIdx.x;
    if (i >= BB * CH_ALL) return;
    int slot = i & (CH_ALL - 1);
    bool is_min = (slot < 128) || (slot >= 256 && slot < 384);
    g_keys[i] = is_min ? 0xFFFFFFFFu : 0x00000000u;
}

// ---------------- kernel 1: transpose img_bev[0]  [C][P] -> [P][C] -----------
__global__ void transpose_kernel(const float* __restrict__ img) {
    __shared__ float tile[32][33];
    int p0 = blockIdx.x * 32;
    int c0 = blockIdx.y * 32;
    int tx = threadIdx.x;   // 0..31
    int ty = threadIdx.y;   // 0..7
#pragma unroll
    for (int j = 0; j < 4; ++j) {
        int c = c0 + ty + j * 8;
        int p = p0 + tx;
        if (p < SPATIAL) tile[ty + j * 8][tx] = img[c * SPATIAL + p];
    }
    __syncthreads();
#pragma unroll
    for (int j = 0; j < 4; ++j) {
        int p = p0 + ty + j * 8;
        int c = c0 + tx;
        if (p < SPATIAL) g_imgT[p * C_C + c] = tile[tx][ty + j * 8];
    }
}

// ---------------- kernel 2: per-batch segment min/max ------------------------
#define MM_CHUNK 256

__device__ __forceinline__ void flush_mm(int b, int c, float mn, float mx) {
    int msl, xsl;
    if (c < 128) { msl = c;             xsl = 128 + c; }
    else         { msl = 256 + c - 128; xsl = 384 + c - 128; }
    atomicMin(&g_keys[b * CH_ALL + msl], enc_f(mn));
    atomicMax(&g_keys[b * CH_ALL + xsl], enc_f(mx));
}

__global__ void __launch_bounds__(256) minmax_kernel(
    const float* __restrict__ lidar,
    const int* __restrict__ batch_idx,
    const int* __restrict__ y_idx,
    const int* __restrict__ x_idx,
    int N)
{
    __shared__ int sb[MM_CHUNK];
    __shared__ int sr[MM_CHUNK];
    int tid = threadIdx.x;
    int n0 = blockIdx.x * MM_CHUNK;
    int cnt = N - n0; if (cnt > MM_CHUNK) cnt = MM_CHUNK;
    if (cnt <= 0) return;

    if (tid < cnt) {
        int n = n0 + tid;
        int b = batch_idx[n];
        int r = b * SPATIAL + y_idx[n] * WW + x_idx[n];
        if (r > SPATIAL - 2) r = SPATIAL - 2;
        sb[tid] = b;
        sr[tid] = r;
    }
    __syncthreads();

    const int c = tid;  // channel 0..255
    float mn = INFINITY, mx = -INFINITY;
    int cur = sb[0];
    for (int i = 0; i < cnt; ++i) {
        int b = sb[i];
        if (b != cur) {                 // block-uniform branch (sorted batches)
            flush_mm(cur, c, mn, mx);
            cur = b; mn = INFINITY; mx = -INFINITY;
        }
        float v = (c < 128) ? lidar[(size_t)(n0 + i) * C_L + c]
                            : g_imgT[(size_t)sr[i] * C_C + (c - 128)];
        mn = fminf(mn, v);
        mx = fmaxf(mx, v);
    }
    flush_mm(cur, c, mn, mx);
}

// ---------------- kernel 3a: gating MLP layer 1 (warp per output) ------------
// Outputs: 2 nets x 4 batches x 170 hidden = 1360 warps = 170 blocks x 8 warps.
__global__ void __launch_bounds__(256) mlp1_kernel(
    const float* __restrict__ Wl1, const float* __restrict__ Wc1)
{
    int gw   = blockIdx.x * 8 + (threadIdx.x >> 5);
    int lane = threadIdx.x & 31;
    int net  = gw / (BB * CH_HID);
    int rem  = gw % (BB * CH_HID);
    int b    = rem / CH_HID;
    int j    = rem % CH_HID;
    const float* W = net ? Wc1 : Wl1;   // [512][170]
    float s = 0.f;
#pragma unroll
    for (int t = 0; t < 16; ++t) {
        int k = lane + 32 * t;
        s = fmaf(dec_f(g_keys[b * CH_ALL + k]), W[k * CH_HID + j], s);
    }
#pragma unroll
    for (int o = 16; o; o >>= 1) s += __shfl_xor_sync(0xffffffffu, s, o);
    if (lane == 0) g_hid[net][b][j] = fmaxf(s, 0.f);
}

// ---------------- kernel 3b: gating MLP layer 2 + sigmoid --------------------
// Outputs: 2 x 4 x 128 = 1024 threads = 4 blocks x 256.
__global__ void __launch_bounds__(256) mlp2_kernel(
    const float* __restrict__ Wl2, const float* __restrict__ Wc2)
{
    int idx = blockIdx.x * 256 + threadIdx.x;   // 0..1023
    int net = idx >> 9;
    int rem = idx & 511;
    int b   = rem >> 7;
    int cc  = rem & 127;
    const float* W2 = net ? Wc2 : Wl2;          // [170][128]
    const float* h  = g_hid[net][b];
    float s = 0.f;
    for (int k = 0; k < CH_HID; ++k) s = fmaf(h[k], W2[k * 128 + cc], s);
    float v = fmaxf(s, 0.f);
    float att = 1.f / (1.f + expf(-v));
    (net ? g_att_c : g_att_l)[b * 128 + cc] = att;
}

// ---------------- kernel 4: fused gate + GEMM1 + ReLU + GEMM2 + ReLU ---------
// 256 threads, 64x256 output tile, per-thread 8 rows x 8 cols as 8x4 packed
// f32x2 accumulators. Weight k-panel [32][256] staged in smem.
#define BM 64
#define SMEM_D (BM * 256 * 4 + 32 * 256 * 4 + 2 * BM * 4)

__device__ __forceinline__ void gemm_f32x2(
    const float4* __restrict__ W4,   // weights [256][256] as float4
    const float* __restrict__ src_s, // [64][256] smem
    float4* wp4,                     // [32][256] smem panel
    u64 acc[8][4], int tid, int ty, int tx)
{
    const ulonglong2* wpU = (const ulonglong2*)wp4;
#pragma unroll 1
    for (int kp = 0; kp < 8; ++kp) {
        __syncthreads();             // previous panel consumers done
#pragma unroll
        for (int i = 0; i < 8; ++i) {
            int idx = tid + i * 256;
            wp4[idx] = W4[kp * 2048 + idx];
        }
        __syncthreads();
#pragma unroll 4
        for (int kq = 0; kq < 16; ++kq) {      // 2 kk per kq
            float2 av[8];
#pragma unroll
            for (int i = 0; i < 8; ++i)
                av[i] = *(const float2*)&src_s[(ty * 8 + i) * 256 + kp * 32 + kq * 2];
#pragma unroll
            for (int t = 0; t < 2; ++t) {
                int kk = kq * 2 + t;
                ulonglong2 B0 = wpU[kk * 64 + tx * 2];
                ulonglong2 B1 = wpU[kk * 64 + tx * 2 + 1];
                u64 b0 = B0.x, b1 = B0.y, b2 = B1.x, b3 = B1.y;
#pragma unroll
                for (int i = 0; i < 8; ++i) {
                    u64 ap = pack_dup(t ? av[i].y : av[i].x);
                    ffma2(acc[i][0], ap, b0);
                    ffma2(acc[i][1], ap, b1);
                    ffma2(acc[i][2], ap, b2);
                    ffma2(acc[i][3], ap, b3);
                }
            }
        }
    }
}

__global__ void __launch_bounds__(256, 2) fused_kernel(
    const float* __restrict__ lidar,
    const int* __restrict__ batch_idx,
    const int* __restrict__ y_idx,
    const int* __restrict__ x_idx,
    const float* __restrict__ Wf1,
    const float* __restrict__ Wf2,
    float* __restrict__ out,
    int N)
{
    extern __shared__ float sm[];
    float* fused_s = sm;                       // [64][256]
    float* wp      = sm + BM * 256;            // [32][256]
    int*   sb      = (int*)(wp + 32 * 256);    // [64]
    int*   sr      = sb + BM;                  // [64]
    float4* fused4 = (float4*)fused_s;
    float4* wp4    = (float4*)wp;

    const int tid = threadIdx.x;
    const int tx = tid & 31;
    const int ty = tid >> 5;
    const int n0 = blockIdx.x * BM;

    if (tid < BM) {
        int n = n0 + tid;
        int b = 0, r = 0;
        if (n < N) {
            b = batch_idx[n];
            r = b * SPATIAL + y_idx[n] * WW + x_idx[n];
            if (r > SPATIAL - 2) r = SPATIAL - 2;
        }
        sb[tid] = b;
        sr[tid] = r;
    }
    __syncthreads();

    // Phase 1: gated feature assembly -> fused_s[m][k]
    const float4* lidar4 = (const float4*)lidar;
    const float4* imgT4  = (const float4*)g_imgT;
    const float4* attl4  = (const float4*)g_att_l;
    const float4* attc4  = (const float4*)g_att_c;
#pragma unroll
    for (int i = 0; i < 8; ++i) {
        int idx = tid + i * 256;     // 0..2047
        int m  = idx >> 5;
        int cg = idx & 31;
        int n  = n0 + m;
        int b  = sb[m];
        float4 L = make_float4(0.f, 0.f, 0.f, 0.f);
        float4 C = L;
        if (n < N) {
            L = lidar4[(size_t)n * 32 + cg];
            C = imgT4[(size_t)sr[m] * 32 + cg];
        }
        float4 gl = attl4[b * 32 + cg];
        float4 gc = attc4[b * 32 + cg];
        fused4[m * 64 + cg]      = make_float4(L.x*gl.x, L.y*gl.y, L.z*gl.z, L.w*gl.w);
        fused4[m * 64 + 32 + cg] = make_float4(C.x*gc.x, C.y*gc.y, C.z*gc.z, C.w*gc.w);
    }
    // (gemm's leading __syncthreads covers these writes)

    // GEMM1: h = relu(fused @ Wf1)
    u64 acc[8][4];
#pragma unroll
    for (int i = 0; i < 8; ++i)
#pragma unroll
        for (int j = 0; j < 4; ++j) acc[i][j] = 0ull;
    gemm_f32x2((const float4*)Wf1, fused_s, wp4, acc, tid, ty, tx);

    __syncthreads();   // all reads of fused_s done before overwrite with h
#pragma unroll
    for (int i = 0; i < 8; ++i) {
        int m = ty * 8 + i;
        float2 p0 = unpk(acc[i][0]), p1 = unpk(acc[i][1]);
        float2 p2 = unpk(acc[i][2]), p3 = unpk(acc[i][3]);
        fused4[m * 64 + tx * 2]     = make_float4(fmaxf(p0.x,0.f), fmaxf(p0.y,0.f),
                                                  fmaxf(p1.x,0.f), fmaxf(p1.y,0.f));
        fused4[m * 64 + tx * 2 + 1] = make_float4(fmaxf(p2.x,0.f), fmaxf(p2.y,0.f),
                                                  fmaxf(p3.x,0.f), fmaxf(p3.y,0.f));
    }

    // GEMM2: out = relu(h @ Wf2)
#pragma unroll
    for (int i = 0; i < 8; ++i)
#pragma unroll
        for (int j = 0; j < 4; ++j) acc[i][j] = 0ull;
    gemm_f32x2((const float4*)Wf2, fused_s, wp4, acc, tid, ty, tx);

    float4* out4 = (float4*)out;
#pragma unroll
    for (int i = 0; i < 8; ++i) {
        int n = n0 + ty * 8 + i;
        if (n < N) {
            float2 p0 = unpk(acc[i][0]), p1 = unpk(acc[i][1]);
            float2 p2 = unpk(acc[i][2]), p3 = unpk(acc[i][3]);
            out4[(size_t)n * 64 + tx * 2]     = make_float4(fmaxf(p0.x,0.f), fmaxf(p0.y,0.f),
                                                            fmaxf(p1.x,0.f), fmaxf(p1.y,0.f));
            out4[(size_t)n * 64 + tx * 2 + 1] = make_float4(fmaxf(p2.x,0.f), fmaxf(p2.y,0.f),
                                                            fmaxf(p3.x,0.f), fmaxf(p3.y,0.f));
        }
    }
}

// ---------------- host launcher ----------------------------------------------
extern "C" void kernel_launch(void* const* d_in, const int* in_sizes, int n_in,
                              void* d_out, int out_size)
{
    int iL = -1, iImg = -1, iB = -1, iY = -1, iX = -1;
    int iWl1 = -1, iWl2 = -1, iWc1 = -1, iWc2 = -1, iWf1 = -1, iWf2 = -1;
    for (int i = 0; i < n_in; ++i) {
        int s = in_sizes[i];
        if      (s == BB * C_C * SPATIAL)      iImg = i;
        else if (s == CH_ALL * CH_HID)         { if (iWl1 < 0) iWl1 = i; else iWc1 = i; }
        else if (s == CH_HID * C_L)            { if (iWl2 < 0) iWl2 = i; else iWc2 = i; }
        else if (s == C_OUT * C_OUT)           { if (iWf1 < 0) iWf1 = i; else iWf2 = i; }
        else if (s % C_L == 0 && s >= 1000000) iL = i;
        else                                   { if (iB < 0) iB = i; else if (iY < 0) iY = i; else iX = i; }
    }
    const float* lidar = (const float*)d_in[iL];
    const float* img   = (const float*)d_in[iImg];
    const int*   bidx  = (const int*)d_in[iB];
    const int*   yidx  = (const int*)d_in[iY];
    const int*   xidx  = (const int*)d_in[iX];
    const float* Wl1   = (const float*)d_in[iWl1];
    const float* Wl2   = (const float*)d_in[iWl2];
    const float* Wc1   = (const float*)d_in[iWc1];
    const float* Wc2   = (const float*)d_in[iWc2];
    const float* Wf1   = (const float*)d_in[iWf1];
    const float* Wf2   = (const float*)d_in[iWf2];
    float* out = (float*)d_out;
    const int N = in_sizes[iL] / C_L;

    cudaFuncSetAttribute(fused_kernel, cudaFuncAttributeMaxDynamicSharedMemorySize, SMEM_D);

    init_keys_kernel<<<(BB * CH_ALL + 255) / 256, 256>>>();
    transpose_kernel<<<dim3((SPATIAL + 31) / 32, C_C / 32), dim3(32, 8)>>>(img);
    minmax_kernel<<<(N + MM_CHUNK - 1) / MM_CHUNK, 256>>>(lidar, bidx, yidx, xidx, N);
    mlp1_kernel<<<CH_HID, 256>>>(Wl1, Wc1);
    mlp2_kernel<<<4, 256>>>(Wl2, Wc2);
    fused_kernel<<<(N + BM - 1) / BM, 256, SMEM_D>>>(lidar, bidx, yidx, xidx, Wf1, Wf2, out, N);
    (void)out_size;
}

// round 4
// speedup vs baseline: 2.1911x; 1.7447x over previous
#include <cuda_runtime.h>
#include <cuda_bf16.h>
#include <math.h>

// Problem constants (fixed-shape problem)
#define BB 4
#define HH_ 180
#define WW 180
#define SPATIAL (HH_ * WW)       // 32400
#define C_L 128
#define C_C 128
#define CH_ALL 512
#define CH_HID 170
#define C_OUT 256

typedef unsigned int u32;
typedef unsigned long long u64;

// ---- fused kernel smem map (bytes) ----
// A  hi: [64m][256k] bf16, 512B rows, xor-swizzled : 0      .. 32767
// A  lo:                                            : 32768  .. 65535
// h  hi: same layout                                : 65536  .. 98303
// h  lo:                                            : 98304  .. 131071
// B  buf0/buf1: [256n][32k hi | 32k lo] 128B rows   : 131072 .. 196607
#define SM_AH 0
#define SM_AL 32768
#define SM_HH 65536
#define SM_B  131072
#define SMEM_TOTAL 196608

// ---------------- device scratch ----------------------------------------------
__device__ __align__(16) float g_imgT[SPATIAL * C_C];     // img batch0 [pixel][chan]
__device__ unsigned g_keys[BB * CH_ALL];
__device__ __align__(16) float g_hid[2][BB][CH_HID];
__device__ __align__(16) float g_att_l[BB * C_L];
__device__ __align__(16) float g_att_c[BB * C_C];
// pre-swizzled weight images: 8 panels x 32KB (rows: [n][32k hi | 32k lo])
__device__ __align__(16) __nv_bfloat16 g_B1[131072];      // 256KB
__device__ __align__(16) __nv_bfloat16 g_B2[131072];

// ---------------- helpers -------------------------------------------------------
__device__ __forceinline__ u32 smem_u32(const void* p) {
    u32 r;
    asm("{ .reg .u64 t; cvta.to.shared.u64 t, %1; cvt.u32.u64 %0, t; }" : "=r"(r) : "l"(p));
    return r;
}
__device__ __forceinline__ void cp16(u32 dst, const void* src) {
    asm volatile("cp.async.cg.shared.global [%0], [%1], 16;" :: "r"(dst), "l"(src) : "memory");
}
__device__ __forceinline__ void cp_commit() { asm volatile("cp.async.commit_group;" ::: "memory"); }
__device__ __forceinline__ void cp_wait0()  { asm volatile("cp.async.wait_group 0;" ::: "memory"); }
__device__ __forceinline__ void cp_wait1()  { asm volatile("cp.async.wait_group 1;" ::: "memory"); }

__device__ __forceinline__ void ldsm4(u32 a, u32 &r0, u32 &r1, u32 &r2, u32 &r3) {
    asm volatile("ldmatrix.sync.aligned.m8n8.x4.shared.b16 {%0,%1,%2,%3}, [%4];"
                 : "=r"(r0), "=r"(r1), "=r"(r2), "=r"(r3) : "r"(a));
}
__device__ __forceinline__ void mma16816(float* c, u32 a0, u32 a1, u32 a2, u32 a3,
                                         u32 b0, u32 b1) {
    asm volatile("mma.sync.aligned.m16n8k16.row.col.f32.bf16.bf16.f32 "
                 "{%0,%1,%2,%3}, {%4,%5,%6,%7}, {%8,%9}, {%0,%1,%2,%3};"
                 : "+f"(c[0]), "+f"(c[1]), "+f"(c[2]), "+f"(c[3])
                 : "r"(a0), "r"(a1), "r"(a2), "r"(a3), "r"(b0), "r"(b1));
}

// pack two fp32 -> bf16x2 word (low16 = v0, high16 = v1), rn
__device__ __forceinline__ u32 pk_bf16(float v0, float v1) {
    u32 r; asm("cvt.rn.bf16x2.f32 %0, %1, %2;" : "=r"(r) : "f"(v1), "f"(v0)); return r;
}
// hi/lo split of a fp32 pair into two bf16x2 words
__device__ __forceinline__ void split2(float v0, float v1, u32 &h, u32 &l) {
    h = pk_bf16(v0, v1);
    float h0 = __uint_as_float(h << 16);
    float h1 = __uint_as_float(h & 0xFFFF0000u);
    l = pk_bf16(v0 - h0, v1 - h1);
}

// Order-preserving float <-> uint encoding for atomic min/max
__device__ __forceinline__ unsigned enc_f(float x) {
    unsigned u = __float_as_uint(x);
    return (u & 0x80000000u) ? ~u : (u | 0x80000000u);
}
__device__ __forceinline__ float dec_f(unsigned k) {
    unsigned u = (k & 0x80000000u) ? (k ^ 0x80000000u) : ~k;
    return __uint_as_float(u);
}

// ---------------- kernel 0: init min/max keys -----------------------------------
__global__ void init_keys_kernel() {
    int i = blockIdx.x * blockDim.x + threadIdx.x;
    if (i >= BB * CH_ALL) return;
    int slot = i & (CH_ALL - 1);
    bool is_min = (slot < 128) || (slot >= 256 && slot < 384);
    g_keys[i] = is_min ? 0xFFFFFFFFu : 0x00000000u;
}

// ---------------- kernel 1: transpose img_bev[0] [C][P] -> [P][C] ---------------
__global__ void transpose_kernel(const float* __restrict__ img) {
    __shared__ float tile[32][33];
    int p0 = blockIdx.x * 32;
    int c0 = blockIdx.y * 32;
    int tx = threadIdx.x, ty = threadIdx.y;
#pragma unroll
    for (int j = 0; j < 4; ++j) {
        int c = c0 + ty + j * 8;
        int p = p0 + tx;
        if (p < SPATIAL) tile[ty + j * 8][tx] = img[c * SPATIAL + p];
    }
    __syncthreads();
#pragma unroll
    for (int j = 0; j < 4; ++j) {
        int p = p0 + ty + j * 8;
        int c = c0 + tx;
        if (p < SPATIAL) g_imgT[p * C_C + c] = tile[tx][ty + j * 8];
    }
}

// ---------------- kernel 2: per-batch segment min/max ---------------------------
#define MM_CHUNK 256
__device__ __forceinline__ void flush_mm(int b, int c, float mn, float mx) {
    int msl, xsl;
    if (c < 128) { msl = c;             xsl = 128 + c; }
    else         { msl = 256 + c - 128; xsl = 384 + c - 128; }
    atomicMin(&g_keys[b * CH_ALL + msl], enc_f(mn));
    atomicMax(&g_keys[b * CH_ALL + xsl], enc_f(mx));
}
__global__ void __launch_bounds__(256) minmax_kernel(
    const float* __restrict__ lidar, const int* __restrict__ batch_idx,
    const int* __restrict__ y_idx, const int* __restrict__ x_idx, int N)
{
    __shared__ int sb[MM_CHUNK];
    __shared__ int sr[MM_CHUNK];
    int tid = threadIdx.x;
    int n0 = blockIdx.x * MM_CHUNK;
    int cnt = N - n0; if (cnt > MM_CHUNK) cnt = MM_CHUNK;
    if (cnt <= 0) return;
    if (tid < cnt) {
        int n = n0 + tid;
        int b = batch_idx[n];
        int r = b * SPATIAL + y_idx[n] * WW + x_idx[n];
        if (r > SPATIAL - 2) r = SPATIAL - 2;
        sb[tid] = b; sr[tid] = r;
    }
    __syncthreads();
    const int c = tid;
    float mn = INFINITY, mx = -INFINITY;
    int cur = sb[0];
    for (int i = 0; i < cnt; ++i) {
        int b = sb[i];
        if (b != cur) { flush_mm(cur, c, mn, mx); cur = b; mn = INFINITY; mx = -INFINITY; }
        float v = (c < 128) ? lidar[(size_t)(n0 + i) * C_L + c]
                            : g_imgT[(size_t)sr[i] * C_C + (c - 128)];
        mn = fminf(mn, v); mx = fmaxf(mx, v);
    }
    flush_mm(cur, c, mn, mx);
}

// ---------------- kernel 3a/3b: tiny gating MLPs --------------------------------
__global__ void __launch_bounds__(256) mlp1_kernel(
    const float* __restrict__ Wl1, const float* __restrict__ Wc1)
{
    int gw   = blockIdx.x * 8 + (threadIdx.x >> 5);
    int lane = threadIdx.x & 31;
    int net  = gw / (BB * CH_HID);
    int rem  = gw % (BB * CH_HID);
    int b    = rem / CH_HID;
    int j    = rem % CH_HID;
    const float* W = net ? Wc1 : Wl1;
    float s = 0.f;
#pragma unroll
    for (int t = 0; t < 16; ++t) {
        int k = lane + 32 * t;
        s = fmaf(dec_f(g_keys[b * CH_ALL + k]), W[k * CH_HID + j], s);
    }
#pragma unroll
    for (int o = 16; o; o >>= 1) s += __shfl_xor_sync(0xffffffffu, s, o);
    if (lane == 0) g_hid[net][b][j] = fmaxf(s, 0.f);
}
__global__ void __launch_bounds__(256) mlp2_kernel(
    const float* __restrict__ Wl2, const float* __restrict__ Wc2)
{
    int idx = blockIdx.x * 256 + threadIdx.x;
    int net = idx >> 9, rem = idx & 511;
    int b = rem >> 7, cc = rem & 127;
    const float* W2 = net ? Wc2 : Wl2;
    const float* h  = g_hid[net][b];
    float s = 0.f;
    for (int k = 0; k < CH_HID; ++k) s = fmaf(h[k], W2[k * 128 + cc], s);
    float v = fmaxf(s, 0.f);
    (net ? g_att_c : g_att_l)[b * 128 + cc] = 1.f / (1.f + expf(-v));
}

// ---------------- kernel 3c: weight prep (transpose + split + pre-swizzle) ------
// Image layout: panel p (k in [32p, 32p+32)), row n (128B): 8 units of 16B,
// unit u holds k8-local block; hi blocks are logical units 0..3, lo 4..7; stored
// unit index = logical ^ (n & 7).  Element e = k & 7 at byte 2e within unit.
__global__ void __launch_bounds__(256) weight_prep_kernel(
    const float* __restrict__ Wf1, const float* __restrict__ Wf2)
{
    int idx = blockIdx.x * 256 + threadIdx.x;   // 2 * 65536
    int mat = idx >> 16;
    int rem = idx & 65535;
    int k = rem >> 8;          // 0..255 input dim
    int n = rem & 255;         // 0..255 output dim
    const float* W = mat ? Wf2 : Wf1;
    float v = W[k * 256 + n];
    u32 hh = pk_bf16(v, 0.f);
    float hf = __uint_as_float(hh << 16);
    u32 ll = pk_bf16(v - hf, 0.f);
    int p = k >> 5, kl = k & 31, k8l = kl >> 3, e = k & 7;
    u32 base = (u32)p * 32768u + (u32)n * 128u + (u32)e * 2u;
    u32 offh = base + ((u32)(k8l ^ (n & 7)) << 4);
    u32 offl = base + ((u32)((k8l + 4) ^ (n & 7)) << 4);
    __nv_bfloat16* img = mat ? g_B2 : g_B1;
    *(unsigned short*)((char*)img + offh) = (unsigned short)(hh & 0xFFFFu);
    *(unsigned short*)((char*)img + offl) = (unsigned short)(ll & 0xFFFFu);
}

// ---------------- fused GEMM stage ------------------------------------------------
// Computes acc += Asm(hi/lo @ Abase) x B(imgs), K=256 in 8 panels of 32,
// cp.async double-buffered.  Warp tile 32m x 64n.
__device__ __forceinline__ void gemm_stage(
    u32 smb, u32 Abase, const uint4* __restrict__ Bimg,
    float acc[2][8][4], int tid, int lane, int wm, int wn)
{
    const u32 Bb = smb + SM_B;
    // preload panel 0 -> buf0
    {
        u32 dst = Bb + (u32)tid * 16u;
        const uint4* s = Bimg + tid;
#pragma unroll
        for (int i = 0; i < 8; ++i) cp16(dst + i * 4096u, s + i * 256);
        cp_commit();
    }
#pragma unroll 1
    for (int p = 0; p < 8; ++p) {
        if (p < 7) {
            u32 dst = Bb + (u32)((p + 1) & 1) * 32768u + (u32)tid * 16u;
            const uint4* s = Bimg + (p + 1) * 2048 + tid;
#pragma unroll
            for (int i = 0; i < 8; ++i) cp16(dst + i * 4096u, s + i * 256);
            cp_commit();
            cp_wait1();
        } else {
            cp_wait0();
        }
        __syncthreads();
        u32 B = Bb + (u32)(p & 1) * 32768u;
#pragma unroll
        for (int s = 0; s < 2; ++s) {
            // ---- A fragments (hi & lo), 2 m16 tiles ----
            int k8 = p * 4 + s * 2 + (lane >> 4);
            int arow = wm + (lane & 15);
            u32 aoff = (u32)arow * 512u + ((u32)(k8 ^ (arow & 7)) << 4);
            u32 ah[2][4], al[2][4];
            ldsm4(Abase + aoff,                 ah[0][0], ah[0][1], ah[0][2], ah[0][3]);
            ldsm4(Abase + aoff + 8192u,         ah[1][0], ah[1][1], ah[1][2], ah[1][3]);
            ldsm4(Abase + 32768u + aoff,        al[0][0], al[0][1], al[0][2], al[0][3]);
            ldsm4(Abase + 32768u + aoff + 8192u,al[1][0], al[1][1], al[1][2], al[1][3]);
            // ---- B fragments: 8 n8-frags, hi & lo ----
            int k8h = s * 2 + (lane >> 4);       // 0..3 (hi logical unit)
            u32 bh[8][2], bl[8][2];
#pragma unroll
            for (int j16 = 0; j16 < 4; ++j16) {
                int brow = wn + j16 * 16 + (lane & 15);
                u32 rb = B + (u32)brow * 128u;
                u32 r0, r1, r2, r3;
                ldsm4(rb + ((u32)(k8h ^ (brow & 7)) << 4), r0, r1, r2, r3);
                bh[2*j16][0] = r0; bh[2*j16][1] = r2;
                bh[2*j16+1][0] = r1; bh[2*j16+1][1] = r3;
                ldsm4(rb + ((u32)((k8h + 4) ^ (brow & 7)) << 4), r0, r1, r2, r3);
                bl[2*j16][0] = r0; bl[2*j16][1] = r2;
                bl[2*j16+1][0] = r1; bl[2*j16+1][1] = r3;
            }
            // ---- 3-term split MMA ----
#pragma unroll
            for (int i = 0; i < 2; ++i)
#pragma unroll
                for (int j = 0; j < 8; ++j) {
                    mma16816(acc[i][j], ah[i][0], ah[i][1], ah[i][2], ah[i][3], bh[j][0], bh[j][1]);
                    mma16816(acc[i][j], al[i][0], al[i][1], al[i][2], al[i][3], bh[j][0], bh[j][1]);
                    mma16816(acc[i][j], ah[i][0], ah[i][1], ah[i][2], ah[i][3], bl[j][0], bl[j][1]);
                }
        }
        __syncthreads();
    }
}

// ---------------- kernel 4: fused gate + GEMM1 + ReLU + GEMM2 + ReLU -------------
__global__ void __launch_bounds__(256, 1) fused_mma_kernel(
    const float* __restrict__ lidar,
    const int* __restrict__ batch_idx,
    const int* __restrict__ y_idx,
    const int* __restrict__ x_idx,
    float* __restrict__ out, int N)
{
    extern __shared__ char sm[];
    const u32 smb = smem_u32(sm);
    const int tid  = threadIdx.x;
    const int lane = tid & 31;
    const int wid  = tid >> 5;
    const int wm   = (wid & 1) * 32;
    const int wn   = (wid >> 1) * 64;

    // ---- phase 1: gather + gate + bf16 split into A smem (swizzled) ----
    {
        int m = tid >> 2, q = tid & 3;          // 4 threads per row, 64 ch each
        int n = blockIdx.x * 64 + m;
        int nn = n < N ? n : N - 1;
        int b = batch_idx[nn];
        const float* src;
        const float* att;
        if (q < 2) { src = lidar + (size_t)nn * C_L; att = g_att_l + b * 128; }
        else {
            int r = b * SPATIAL + y_idx[nn] * WW + x_idx[nn];
            if (r > SPATIAL - 2) r = SPATIAL - 2;
            src = g_imgT + (size_t)r * C_C; att = g_att_c + b * 128;
        }
        const float4* s4 = (const float4*)src;
        const float4* g4 = (const float4*)att;
        int ho = (q & 1) * 16;                   // float4 offset within source
        u32 rowb = (u32)m * 512u;
        u32 xm = (u32)(m & 7);
#pragma unroll
        for (int i = 0; i < 8; ++i) {
            float4 a0 = s4[ho + 2*i], a1 = s4[ho + 2*i + 1];
            float4 q0 = g4[ho + 2*i], q1 = g4[ho + 2*i + 1];
            float v0 = a0.x*q0.x, v1 = a0.y*q0.y, v2 = a0.z*q0.z, v3 = a0.w*q0.w;
            float v4 = a1.x*q1.x, v5 = a1.y*q1.y, v6 = a1.z*q1.z, v7 = a1.w*q1.w;
            uint4 H, L;
            split2(v0, v1, H.x, L.x); split2(v2, v3, H.y, L.y);
            split2(v4, v5, H.z, L.z); split2(v6, v7, H.w, L.w);
            u32 k8 = (u32)(q * 8 + i);          // 0..31
            u32 off = rowb + ((k8 ^ xm) << 4);
            *(uint4*)(sm + SM_AH + off) = H;
            *(uint4*)(sm + SM_AL + off) = L;
        }
    }
    // (first __syncthreads inside gemm_stage covers A writes)

    float acc[2][8][4];
#pragma unroll
    for (int i = 0; i < 2; ++i)
#pragma unroll
        for (int j = 0; j < 8; ++j)
#pragma unroll
            for (int c = 0; c < 4; ++c) acc[i][j][c] = 0.f;

    // ---- GEMM1 ----
    gemm_stage(smb, smb + SM_AH, (const uint4*)g_B1, acc, tid, lane, wm, wn);

    // ---- epilogue 1: relu + split -> h smem ----
    {
#pragma unroll
        for (int i = 0; i < 2; ++i) {
            int r0 = wm + 16 * i + (lane >> 2);
#pragma unroll
            for (int j = 0; j < 8; ++j) {
                float* c = acc[i][j];
                u32 k8 = (u32)((wn >> 3) + j);
                u32 eb = (u32)(lane & 3) * 4u;
                float v0 = fmaxf(c[0], 0.f), v1 = fmaxf(c[1], 0.f);
                float v2 = fmaxf(c[2], 0.f), v3 = fmaxf(c[3], 0.f);
                u32 h0, l0, h1, l1;
                split2(v0, v1, h0, l0);
                split2(v2, v3, h1, l1);
                u32 o0 = (u32)r0 * 512u + ((k8 ^ (u32)(r0 & 7)) << 4) + eb;
                int r1 = r0 + 8;
                u32 o1 = (u32)r1 * 512u + ((k8 ^ (u32)(r1 & 7)) << 4) + eb;
                *(u32*)(sm + SM_HH + o0) = h0;
                *(u32*)(sm + SM_HH + 32768 + o0) = l0;
                *(u32*)(sm + SM_HH + o1) = h1;
                *(u32*)(sm + SM_HH + 32768 + o1) = l1;
            }
        }
    }
    __syncthreads();

#pragma unroll
    for (int i = 0; i < 2; ++i)
#pragma unroll
        for (int j = 0; j < 8; ++j)
#pragma unroll
            for (int c = 0; c < 4; ++c) acc[i][j][c] = 0.f;

    // ---- GEMM2 ----
    gemm_stage(smb, smb + SM_HH, (const uint4*)g_B2, acc, tid, lane, wm, wn);

    // ---- epilogue 2: relu -> gmem ----
    {
        int mbase = blockIdx.x * 64;
#pragma unroll
        for (int i = 0; i < 2; ++i) {
            int r0 = mbase + wm + 16 * i + (lane >> 2);
            int r1 = r0 + 8;
#pragma unroll
            for (int j = 0; j < 8; ++j) {
                float* c = acc[i][j];
                int col = wn + 8 * j + 2 * (lane & 3);
                if (r0 < N) {
                    float2 v = make_float2(fmaxf(c[0], 0.f), fmaxf(c[1], 0.f));
                    *(float2*)(out + (size_t)r0 * 256 + col) = v;
                }
                if (r1 < N) {
                    float2 v = make_float2(fmaxf(c[2], 0.f), fmaxf(c[3], 0.f));
                    *(float2*)(out + (size_t)r1 * 256 + col) = v;
                }
            }
        }
    }
}

// ---------------- host launcher ---------------------------------------------------
extern "C" void kernel_launch(void* const* d_in, const int* in_sizes, int n_in,
                              void* d_out, int out_size)
{
    int iL = -1, iImg = -1, iB = -1, iY = -1, iX = -1;
    int iWl1 = -1, iWl2 = -1, iWc1 = -1, iWc2 = -1, iWf1 = -1, iWf2 = -1;
    for (int i = 0; i < n_in; ++i) {
        int s = in_sizes[i];
        if      (s == BB * C_C * SPATIAL)      iImg = i;
        else if (s == CH_ALL * CH_HID)         { if (iWl1 < 0) iWl1 = i; else iWc1 = i; }
        else if (s == CH_HID * C_L)            { if (iWl2 < 0) iWl2 = i; else iWc2 = i; }
        else if (s == C_OUT * C_OUT)           { if (iWf1 < 0) iWf1 = i; else iWf2 = i; }
        else if (s % C_L == 0 && s >= 1000000) iL = i;
        else                                   { if (iB < 0) iB = i; else if (iY < 0) iY = i; else iX = i; }
    }
    const float* lidar = (const float*)d_in[iL];
    const float* img   = (const float*)d_in[iImg];
    const int*   bidx  = (const int*)d_in[iB];
    const int*   yidx  = (const int*)d_in[iY];
    const int*   xidx  = (const int*)d_in[iX];
    const float* Wl1   = (const float*)d_in[iWl1];
    const float* Wl2   = (const float*)d_in[iWl2];
    const float* Wc1   = (const float*)d_in[iWc1];
    const float* Wc2   = (const float*)d_in[iWc2];
    const float* Wf1   = (const float*)d_in[iWf1];
    const float* Wf2   = (const float*)d_in[iWf2];
    float* out = (float*)d_out;
    const int N = in_sizes[iL] / C_L;

    cudaFuncSetAttribute(fused_mma_kernel, cudaFuncAttributeMaxDynamicSharedMemorySize, SMEM_TOTAL);

    init_keys_kernel<<<(BB * CH_ALL + 255) / 256, 256>>>();
    transpose_kernel<<<dim3((SPATIAL + 31) / 32, C_C / 32), dim3(32, 8)>>>(img);
    weight_prep_kernel<<<512, 256>>>(Wf1, Wf2);
    minmax_kernel<<<(N + MM_CHUNK - 1) / MM_CHUNK, 256>>>(lidar, bidx, yidx, xidx, N);
    mlp1_kernel<<<CH_HID, 256>>>(Wl1, Wc1);
    mlp2_kernel<<<4, 256>>>(Wl2, Wc2);
    fused_mma_kernel<<<(N + 63) / 64, 256, SMEM_TOTAL>>>(lidar, bidx, yidx, xidx, out, N);
    (void)out_size;
}